// round 14
// baseline (speedup 1.0000x reference)
#include <cuda_runtime.h>
#include <math.h>

#define B_ 2048
#define D_ 512
#define T_ 16
#define H_ 1024
#define K_ 50
#define NSWEEP 5

// ------------------- device scratch (no allocations allowed) -------------------
__device__ float g_s[B_ * H_];        // (1 - tanh^2(z)) * W2  [B, H]
__device__ float g_grad[B_ * D_];     // grad_x                [B, D]
__device__ float g_d2[B_ * B_];       // pairwise sq distances [B, B]
__device__ float g_sq[B_];            // row squared norms
__device__ int   g_ni[B_ * K_];       // kNN indices           [B, K]
__device__ float g_G[B_ * K_ * K_];   // Gram matrices         [B, 50, 50]
__device__ float g_mean[B_ * D_];     // neighbor column means [B, 512]
__device__ float g_w[B_ * K_];        // target vector         [B, 50]
__device__ float g_res[B_];           // per-batch result

// ------------------- squared norms -------------------
__global__ __launch_bounds__(256) void k_sq(const float* __restrict__ p) {
  int w = (blockIdx.x * 256 + threadIdx.x) >> 5;
  int lane = threadIdx.x & 31;
  const float* row = p + w * D_;
  float s = 0.f;
  for (int d = lane; d < D_; d += 32) { float v = row[d]; s += v * v; }
#pragma unroll
  for (int o = 16; o > 0; o >>= 1) s += __shfl_xor_sync(0xffffffffu, s, o);
  if (lane == 0) g_sq[w] = s;
}

// ------------------- GEMM 1: z = [x|t] @ W1 + b1 ; s = (1-tanh^2 z) * W2 -------------------
__global__ __launch_bounds__(256) void k_fwd(const float* __restrict__ xin,
                                             const float* __restrict__ tin,
                                             const float* __restrict__ W1,
                                             const float* __restrict__ b1,
                                             const float* __restrict__ W2) {
  __shared__ __align__(16) float As[16][68];
  __shared__ __align__(16) float Bs[16][68];
  const int tid = threadIdx.x, tx = tid & 15, ty = tid >> 4;
  const int n0 = blockIdx.x * 64, m0 = blockIdx.y * 64;
  float acc[16];
#pragma unroll
  for (int i = 0; i < 16; i++) acc[i] = 0.f;
  for (int k0 = 0; k0 < 528; k0 += 16) {
#pragma unroll
    for (int i = 0; i < 4; i++) {
      int e = tid + i * 256;
      int kk = e & 15, mm = e >> 4;
      int kc = k0 + kk;
      As[kk][mm] = (kc < 512) ? xin[(m0 + mm) * 512 + kc]
                              : tin[(m0 + mm) * 16 + (kc - 512)];
      int nn = e & 63, kb = e >> 6;
      Bs[kb][nn] = W1[(k0 + kb) * 1024 + n0 + nn];
    }
    __syncthreads();
#pragma unroll
    for (int kk = 0; kk < 16; kk++) {
      float4 a4 = *(const float4*)&As[kk][ty * 4];
      float4 b4 = *(const float4*)&Bs[kk][tx * 4];
      float av[4] = {a4.x, a4.y, a4.z, a4.w};
      float bv[4] = {b4.x, b4.y, b4.z, b4.w};
#pragma unroll
      for (int i = 0; i < 4; i++)
#pragma unroll
        for (int j = 0; j < 4; j++) acc[i * 4 + j] += av[i] * bv[j];
    }
    __syncthreads();
  }
#pragma unroll
  for (int i = 0; i < 4; i++) {
    int m = m0 + ty * 4 + i;
    float o[4];
#pragma unroll
    for (int j = 0; j < 4; j++) {
      int n = n0 + tx * 4 + j;
      float z = acc[i * 4 + j] + b1[n];
      float h = tanhf(z);
      o[j] = (1.f - h * h) * W2[n];
    }
    *(float4*)&g_s[m * 1024 + n0 + tx * 4] = make_float4(o[0], o[1], o[2], o[3]);
  }
}

// ------------------- GEMM 2: grad = s @ W1[:512]^T -------------------
__global__ __launch_bounds__(256) void k_grad(const float* __restrict__ W1) {
  __shared__ __align__(16) float As[16][68];
  __shared__ __align__(16) float Bs[16][68];
  const int tid = threadIdx.x, tx = tid & 15, ty = tid >> 4;
  const int n0 = blockIdx.x * 64, m0 = blockIdx.y * 64;
  float acc[16];
#pragma unroll
  for (int i = 0; i < 16; i++) acc[i] = 0.f;
  for (int k0 = 0; k0 < 1024; k0 += 16) {
#pragma unroll
    for (int i = 0; i < 4; i++) {
      int e = tid + i * 256;
      int kk = e & 15, mm = e >> 4;
      As[kk][mm] = g_s[(m0 + mm) * 1024 + k0 + kk];
      Bs[kk][mm] = W1[(n0 + mm) * 1024 + k0 + kk];  // B[k][n] = W1[n][k]
    }
    __syncthreads();
#pragma unroll
    for (int kk = 0; kk < 16; kk++) {
      float4 a4 = *(const float4*)&As[kk][ty * 4];
      float4 b4 = *(const float4*)&Bs[kk][tx * 4];
      float av[4] = {a4.x, a4.y, a4.z, a4.w};
      float bv[4] = {b4.x, b4.y, b4.z, b4.w};
#pragma unroll
      for (int i = 0; i < 4; i++)
#pragma unroll
        for (int j = 0; j < 4; j++) acc[i * 4 + j] += av[i] * bv[j];
    }
    __syncthreads();
  }
#pragma unroll
  for (int i = 0; i < 4; i++) {
    int m = m0 + ty * 4 + i;
    *(float4*)&g_grad[m * 512 + n0 + tx * 4] =
        make_float4(acc[i * 4 + 0], acc[i * 4 + 1], acc[i * 4 + 2], acc[i * 4 + 3]);
  }
}

// ------------------- GEMM 3 (symmetric): only upper-triangle 64x64 tiles -------------------
__global__ __launch_bounds__(256) void k_d2(const float* __restrict__ p) {
  __shared__ __align__(16) float As[16][68];
  __shared__ __align__(16) float Bs[16][68];
  int bm = 0, bn;
  {
    int rem = blockIdx.x, cnt = 32;
    while (rem >= cnt) { rem -= cnt; bm++; cnt--; }
    bn = bm + rem;
  }
  const int tid = threadIdx.x, tx = tid & 15, ty = tid >> 4;
  const int m0 = bm * 64, n0 = bn * 64;
  float acc[16];
#pragma unroll
  for (int i = 0; i < 16; i++) acc[i] = 0.f;
  for (int k0 = 0; k0 < 512; k0 += 16) {
#pragma unroll
    for (int i = 0; i < 4; i++) {
      int e = tid + i * 256;
      int kk = e & 15, mm = e >> 4;
      As[kk][mm] = p[(m0 + mm) * 512 + k0 + kk];
      Bs[kk][mm] = p[(n0 + mm) * 512 + k0 + kk];
    }
    __syncthreads();
#pragma unroll
    for (int kk = 0; kk < 16; kk++) {
      float4 a4 = *(const float4*)&As[kk][ty * 4];
      float4 b4 = *(const float4*)&Bs[kk][tx * 4];
      float av[4] = {a4.x, a4.y, a4.z, a4.w};
      float bv[4] = {b4.x, b4.y, b4.z, b4.w};
#pragma unroll
      for (int i = 0; i < 4; i++)
#pragma unroll
        for (int j = 0; j < 4; j++) acc[i * 4 + j] += av[i] * bv[j];
    }
    __syncthreads();
  }
#pragma unroll
  for (int i = 0; i < 4; i++) {
    int m = m0 + ty * 4 + i;
    float sm = g_sq[m];
    float o[4];
#pragma unroll
    for (int j = 0; j < 4; j++) {
      int n = n0 + tx * 4 + j;
      o[j] = sm + g_sq[n] - 2.f * acc[i * 4 + j];
    }
    *(float4*)&g_d2[m * 2048 + n0 + tx * 4] = make_float4(o[0], o[1], o[2], o[3]);
    if (bm != bn) {
#pragma unroll
      for (int j = 0; j < 4; j++) g_d2[(n0 + tx * 4 + j) * 2048 + m] = o[j];
    }
  }
}

// ------------------- exact top-50 via 2-level radix select -------------------
__device__ __forceinline__ void find_cross(const unsigned int* hist, unsigned int target,
                                           unsigned int* warpsum,
                                           unsigned int* out_thr, unsigned int* out_base,
                                           int tid) {
  unsigned int loc[8], csum = 0;
#pragma unroll
  for (int i = 0; i < 8; i++) { loc[i] = hist[tid * 8 + i]; csum += loc[i]; }
  int lane = tid & 31, wid = tid >> 5;
  unsigned int v = csum;
#pragma unroll
  for (int o = 1; o < 32; o <<= 1) {
    unsigned int n = __shfl_up_sync(0xffffffffu, v, o);
    if (lane >= o) v += n;
  }
  if (lane == 31) warpsum[wid] = v;
  __syncthreads();
  if (tid < 8) {
    unsigned int w = warpsum[tid];
#pragma unroll
    for (int o = 1; o < 8; o <<= 1) {
      unsigned int n = __shfl_up_sync(0xffu, w, o);
      if (tid >= o) w += n;
    }
    warpsum[tid] = w;
  }
  __syncthreads();
  unsigned int excl = v - csum + (wid ? warpsum[wid - 1] : 0u);
  unsigned int run = excl;
#pragma unroll
  for (int i = 0; i < 8; i++) {
    unsigned int c2 = loc[i];
    if (run < target && run + c2 >= target) { *out_thr = tid * 8 + i; *out_base = run; }
    run += c2;
  }
  __syncthreads();
}

__global__ __launch_bounds__(256) void k_topk() {
  __shared__ unsigned int keys[2048];
  __shared__ unsigned int hist[2048];
  __shared__ unsigned int warpsum[8];
  __shared__ unsigned int s_thr1, s_base1, s_thr2, s_base2, s_cnt, s_cand;
  __shared__ unsigned int cand_key[256];
  __shared__ int cand_idx[256];

  const int row = blockIdx.x, tid = threadIdx.x;
  for (int e = tid; e < 2048; e += 256) {
    unsigned int u = __float_as_uint(g_d2[row * 2048 + e]);
    u = (u & 0x80000000u) ? ~u : (u | 0x80000000u);
    keys[e] = u;
    hist[e] = 0u;
  }
  if (tid == 0) { s_cnt = 0u; s_cand = 0u; }
  __syncthreads();
  for (int e = tid; e < 2048; e += 256) atomicAdd(&hist[keys[e] >> 21], 1u);
  __syncthreads();
  find_cross(hist, K_, warpsum, &s_thr1, &s_base1, tid);
  const unsigned int thr1 = s_thr1, base1 = s_base1;
  for (int e = tid; e < 2048; e += 256) hist[e] = 0u;
  __syncthreads();
  for (int e = tid; e < 2048; e += 256) {
    unsigned int u = keys[e];
    if ((u >> 21) == thr1) atomicAdd(&hist[(u >> 10) & 0x7FFu], 1u);
  }
  __syncthreads();
  find_cross(hist, K_ - base1, warpsum, &s_thr2, &s_base2, tid);
  const unsigned int thr10 = (thr1 << 11) | s_thr2;
  for (int e = tid; e < 2048; e += 256) {
    unsigned int u = keys[e];
    unsigned int hi = u >> 10;
    if (hi < thr10) {
      unsigned int pos = atomicAdd(&s_cnt, 1u);
      g_ni[row * K_ + pos] = e;
    } else if (hi == thr10) {
      unsigned int pos = atomicAdd(&s_cand, 1u);
      if (pos < 256u) { cand_key[pos] = u; cand_idx[pos] = e; }
    }
  }
  __syncthreads();
  const int nc = (int)min(s_cand, 256u);
  const int base = (int)s_cnt;
  const int need = K_ - base;
  if (tid < nc) {
    unsigned int ki = cand_key[tid];
    int ci = cand_idx[tid];
    int rank = 0;
    for (int j = 0; j < nc; j++) {
      unsigned int kj = cand_key[j];
      int cj = cand_idx[j];
      rank += (kj < ki) || (kj == ki && cj < ci);
    }
    if (rank < need) g_ni[row * K_ + base + rank] = ci;
  }
}

// ------------------- Gram only (needs g_ni, NOT g_grad): G + column means ----------------
__device__ __forceinline__ void accum_tile(float* acc, const float (*Cs)[132], int r0, int q0) {
#pragma unroll 4
  for (int d = 0; d < 128; d += 4) {
    float4 ar[4], br[4];
#pragma unroll
    for (int i = 0; i < 4; i++) ar[i] = *(const float4*)&Cs[r0 + i][d];
#pragma unroll
    for (int j = 0; j < 4; j++) br[j] = *(const float4*)&Cs[q0 + j][d];
#pragma unroll
    for (int i = 0; i < 4; i++)
#pragma unroll
      for (int j = 0; j < 4; j++)
        acc[i * 4 + j] += ar[i].x * br[j].x + ar[i].y * br[j].y +
                          ar[i].z * br[j].z + ar[i].w * br[j].w;
  }
}

__global__ __launch_bounds__(128) void k_gramG(const float* __restrict__ pert) {
  __shared__ __align__(16) float Cs[52][132];
  __shared__ int nidx[50];

  const int b = blockIdx.x, tid = threadIdx.x;
  if (tid < 50) nidx[tid] = g_ni[b * K_ + tid];
  for (int dd = tid; dd < 132; dd += 128) { Cs[50][dd] = 0.f; Cs[51][dd] = 0.f; }

  int tr = 0, tq = 0;
  const bool hasT = (tid < 91);
  if (hasT) {
    int rem = tid, cnt = 13;
    while (rem >= cnt) { rem -= cnt; tr++; cnt--; }
    tq = tr + rem;
  }

  float acc0[16];
#pragma unroll
  for (int i = 0; i < 16; i++) acc0[i] = 0.f;
  __syncthreads();

  for (int c = 0; c < 4; c++) {
    for (int e = tid; e < 1600; e += 128) {
      int row = e >> 5;
      int c4 = (e & 31) << 2;
      float4 v = *(const float4*)&pert[nidx[row] * 512 + c * 128 + c4];
      *(float4*)&Cs[row][c4] = v;
    }
    __syncthreads();
    {
      int d = tid;
      float sm = 0.f;
#pragma unroll 10
      for (int k = 0; k < 50; k++) sm += Cs[k][d];
      sm *= (1.0f / 50.0f);
      g_mean[b * 512 + c * 128 + d] = sm;          // export for k_w
      for (int k = 0; k < 50; k++) Cs[k][d] -= sm;
    }
    __syncthreads();
    if (hasT) accum_tile(acc0, Cs, tr * 4, tq * 4);
    __syncthreads();
  }
  float* Gout = &g_G[b * (K_ * K_)];
  if (hasT) {
    int r0 = tr * 4, q0 = tq * 4;
#pragma unroll
    for (int i = 0; i < 4; i++)
#pragma unroll
      for (int j = 0; j < 4; j++) {
        int r = r0 + i, q = q0 + j;
        if (r < 50 && q < 50) {
          float v = acc0[i * 4 + j];
          Gout[r * 50 + q] = v;
          Gout[q * 50 + r] = v;
        }
      }
  }
}

// ------------------- w = C_centered @ g  ==  dot(P_row, g) - mean.g  -------------------
__global__ __launch_bounds__(128) void k_w(const float* __restrict__ pert) {
  __shared__ __align__(16) float gsm[512];
  __shared__ int nidx[50];
  __shared__ float red[4];
  __shared__ float s_mdot;

  const int b = blockIdx.x, tid = threadIdx.x;
  const int lane = tid & 31, wq = tid >> 5;
  if (tid < 50) nidx[tid] = g_ni[b * K_ + tid];

  float part = 0.f;
  for (int d = tid; d < 512; d += 128) {
    float gv = g_grad[b * 512 + d];
    gsm[d] = gv;
    part += gv * g_mean[b * 512 + d];
  }
#pragma unroll
  for (int o = 16; o > 0; o >>= 1) part += __shfl_xor_sync(0xffffffffu, part, o);
  if (lane == 0) red[wq] = part;
  __syncthreads();
  if (tid == 0) s_mdot = (red[0] + red[1]) + (red[2] + red[3]);
  __syncthreads();
  const float mdot = s_mdot;

  for (int row = wq; row < 50; row += 4) {
    const float4* rp = (const float4*)&pert[nidx[row] * 512];
    const float4* gp = (const float4*)gsm;
    float s = 0.f;
#pragma unroll
    for (int i = lane; i < 128; i += 32) {
      float4 a = rp[i], g4 = gp[i];
      s += a.x * g4.x + a.y * g4.y + a.z * g4.z + a.w * g4.w;
    }
#pragma unroll
    for (int o = 16; o > 0; o >>= 1) s += __shfl_xor_sync(0xffffffffu, s, o);
    if (lane == 0) g_w[b * K_ + row] = s - mdot;
  }
}

// ------------------- Jacobi: 2 problems per warp (ILP), frozen R13 math per problem -----
__global__ __launch_bounds__(64) void k_jacobi() {
  __shared__ float Gm[4][50][53];
  __shared__ float wv[4][52];
  __shared__ float2 cs[4][32];

  const int tid = threadIdx.x;
  const int W = tid >> 5;            // warp 0..1
  const int lane = tid & 31;
  const int PA = 2 * W, PB = 2 * W + 1;
  const int bA = blockIdx.x * 4 + PA;
  const int bB = blockIdx.x * 4 + PB;
  float (* __restrict__ GA)[53] = Gm[PA];
  float (* __restrict__ GB)[53] = Gm[PB];
  float* __restrict__ wA = wv[PA];
  float* __restrict__ wB = wv[PB];
  float2* __restrict__ csA = cs[PA];
  float2* __restrict__ csB = cs[PB];

  {
    const float* GinA = &g_G[bA * (K_ * K_)];
    const float* GinB = &g_G[bB * (K_ * K_)];
    for (int e = lane; e < 2500; e += 32) {
      int rr = e / 50, cc = e % 50;
      GA[rr][cc] = GinA[e];
      GB[rr][cc] = GinB[e];
    }
    if (lane < 25) {
      wA[lane] = g_w[bA * K_ + lane];
      wA[lane + 25] = g_w[bA * K_ + lane + 25];
      wB[lane] = g_w[bB * K_ + lane];
      wB[lane + 25] = g_w[bB * K_ + lane + 25];
    }
  }

  // lane's off-diagonal block list: 300 blocks (a<b), ids lane+32*it
  int abA_[10], abB_[10];
#pragma unroll
  for (int it = 0; it < 10; it++) {
    int idx = lane + 32 * it;
    if (idx < 300) {
      int rem = idx, a = 0;
      while (rem >= 24 - a) { rem -= (24 - a); a++; }
      abA_[it] = a;
      abB_[it] = a + 1 + rem;
    } else {
      abA_[it] = -1;
      abB_[it] = 1;
    }
  }
  __syncwarp();

  for (int sw = 0; sw < NSWEEP; sw++) {
    for (int r = 0; r < 49; r++) {
      __syncwarp();
      // params for both problems (indices shared)
      float cA = 1.f, sA = 0.f, cB = 1.f, sB = 0.f;
      if (lane < 25) {
        int p, q;
        if (lane == 0) { p = 49; q = r; }
        else {
          int rp_ = r + lane; p = (rp_ >= 49) ? rp_ - 49 : rp_;
          int rq_ = r - lane; q = (rq_ < 0) ? rq_ + 49 : rq_;
        }
        int mn = min(p, q), mx = max(p, q);
        // problem A
        {
          float app = GA[p][p], aqq = GA[q][q], apq = GA[mn][mx];
          if (apq * apq > 1e-6f * app * aqq) {
            float tau = __fdividef(aqq - app, 2.0f * apq);
            float tt = __fdividef(copysignf(1.0f, tau),
                                  fabsf(tau) + sqrtf(fmaf(tau, tau, 1.0f)));
            cA = rsqrtf(fmaf(tt, tt, 1.0f));
            sA = tt * cA;
            float t00 = cA * app - sA * apq, t01 = cA * apq - sA * aqq;
            float t10 = sA * app + cA * apq, t11 = sA * apq + cA * aqq;
            GA[p][p] = cA * t00 - sA * t01;
            GA[q][q] = sA * t10 + cA * t11;
            GA[mn][mx] = 0.0f;
            float wp = wA[p], wq = wA[q];
            wA[p] = cA * wp - sA * wq;
            wA[q] = sA * wp + cA * wq;
          }
        }
        // problem B (independent chain)
        {
          float app = GB[p][p], aqq = GB[q][q], apq = GB[mn][mx];
          if (apq * apq > 1e-6f * app * aqq) {
            float tau = __fdividef(aqq - app, 2.0f * apq);
            float tt = __fdividef(copysignf(1.0f, tau),
                                  fabsf(tau) + sqrtf(fmaf(tau, tau, 1.0f)));
            cB = rsqrtf(fmaf(tt, tt, 1.0f));
            sB = tt * cB;
            float t00 = cB * app - sB * apq, t01 = cB * apq - sB * aqq;
            float t10 = sB * app + cB * apq, t11 = sB * apq + cB * aqq;
            GB[p][p] = cB * t00 - sB * t01;
            GB[q][q] = sB * t10 + cB * t11;
            GB[mn][mx] = 0.0f;
            float wp = wB[p], wq = wB[q];
            wB[p] = cB * wp - sB * wq;
            wB[q] = sB * wp + cB * wq;
          }
        }
      }
      csA[lane] = make_float2(cA, sA);
      csB[lane] = make_float2(cB, sB);
      __syncwarp();
      // off-diag blocks: indices computed ONCE, applied to both problems
#pragma unroll
      for (int it = 0; it < 10; it++) {
        int a = abA_[it];
        bool ok = (a >= 0);
        int aa = ok ? a : 0;
        int bb = abB_[it];
        int pa, qa, pb, qb;
        if (aa == 0) { pa = 49; qa = r; }
        else {
          int v1 = r + aa; pa = (v1 >= 49) ? v1 - 49 : v1;
          int v2 = r - aa; qa = (v2 < 0) ? v2 + 49 : v2;
        }
        {
          int v1 = r + bb; pb = (v1 >= 49) ? v1 - 49 : v1;
          int v2 = r - bb; qb = (v2 < 0) ? v2 + 49 : v2;
        }
        int i00 = min(pa, pb), j00 = max(pa, pb);
        int i01 = min(pa, qb), j01 = max(pa, qb);
        int i10 = min(qa, pb), j10 = max(qa, pb);
        int i11 = min(qa, qb), j11 = max(qa, qb);
        // problem A
        {
          float2 ra = csA[aa], rb = csA[bb];
          float ca = ra.x, sa = ra.y, cb = rb.x, sb = rb.y;
          float a00 = GA[i00][j00], a01 = GA[i01][j01];
          float a10 = GA[i10][j10], a11 = GA[i11][j11];
          float t00 = ca * a00 - sa * a10, t01 = ca * a01 - sa * a11;
          float t10 = sa * a00 + ca * a10, t11 = sa * a01 + ca * a11;
          float n00 = cb * t00 - sb * t01, n01 = sb * t00 + cb * t01;
          float n10 = cb * t10 - sb * t11, n11 = sb * t10 + cb * t11;
          if (ok) {
            GA[i00][j00] = n00; GA[i01][j01] = n01;
            GA[i10][j10] = n10; GA[i11][j11] = n11;
          }
        }
        // problem B (independent chain interleaves with A's latency)
        {
          float2 ra = csB[aa], rb = csB[bb];
          float ca = ra.x, sa = ra.y, cb = rb.x, sb = rb.y;
          float a00 = GB[i00][j00], a01 = GB[i01][j01];
          float a10 = GB[i10][j10], a11 = GB[i11][j11];
          float t00 = ca * a00 - sa * a10, t01 = ca * a01 - sa * a11;
          float t10 = sa * a00 + ca * a10, t11 = sa * a01 + ca * a11;
          float n00 = cb * t00 - sb * t01, n01 = sb * t00 + cb * t01;
          float n10 = cb * t10 - sb * t11, n11 = sb * t10 + cb * t11;
          if (ok) {
            GB[i00][j00] = n00; GB[i01][j01] = n01;
            GB[i10][j10] = n10; GB[i11][j11] = n11;
          }
        }
      }
    }
  }
  __syncwarp();

  // top-16 selection for both problems
#pragma unroll
  for (int pr = 0; pr < 2; pr++) {
    float (* __restrict__ G)[53] = pr ? GB : GA;
    float* __restrict__ w = pr ? wB : wA;
    const int b = pr ? bB : bA;
    float part = 0.f;
#pragma unroll
    for (int h = 0; h < 2; h++) {
      int i = lane + 32 * h;
      if (i < 50) {
        float li = G[i][i];
        int rank = 0;
#pragma unroll 10
        for (int j = 0; j < 50; j++) {
          float lj = G[j][j];
          rank += (lj > li) || (lj == li && j < i);
        }
        if (rank < 16) part += w[i] * w[i] / li;
      }
    }
#pragma unroll
    for (int o = 16; o > 0; o >>= 1) part += __shfl_xor_sync(0xffffffffu, part, o);
    if (lane == 0) g_res[b] = part;
  }
}

// ------------------- deterministic reduce -------------------
__global__ __launch_bounds__(256) void k_reduce(float* __restrict__ out) {
  __shared__ float sm[256];
  int tid = threadIdx.x;
  float s = 0.f;
  for (int i = tid; i < B_; i += 256) s += g_res[i];
  sm[tid] = s;
  __syncthreads();
  for (int o = 128; o > 0; o >>= 1) {
    if (tid < o) sm[tid] += sm[tid + o];
    __syncthreads();
  }
  if (tid == 0) out[0] = sm[0] / (float)B_;
}

// ------------------- launch: overlap (fwd/grad || sq/d2/topk/gramG) -------------------
extern "C" void kernel_launch(void* const* d_in, const int* in_sizes, int n_in,
                              void* d_out, int out_size) {
  const float* x    = (const float*)d_in[0];
  const float* t    = (const float*)d_in[1];
  const float* pert = (const float*)d_in[2];
  const float* W1   = (const float*)d_in[3];
  const float* b1   = (const float*)d_in[4];
  const float* W2   = (const float*)d_in[5];
  float* out = (float*)d_out;

  static cudaStream_t s1 = nullptr;
  static cudaEvent_t ev_fork = nullptr, ev_join = nullptr;
  if (s1 == nullptr) {
    cudaStreamCreateWithFlags(&s1, cudaStreamNonBlocking);
    cudaEventCreateWithFlags(&ev_fork, cudaEventDisableTiming);
    cudaEventCreateWithFlags(&ev_join, cudaEventDisableTiming);
  }

  cudaEventRecord(ev_fork, 0);
  cudaStreamWaitEvent(s1, ev_fork, 0);

  // GEMM arm (s1)
  k_fwd <<<dim3(H_ / 64, B_ / 64), 256, 0, s1>>>(x, t, W1, b1, W2);
  k_grad<<<dim3(D_ / 64, B_ / 64), 256, 0, s1>>>(W1);

  // kNN arm (default)
  k_sq   <<<B_ / 8, 256>>>(pert);
  k_d2   <<<528, 256>>>(pert);
  k_topk <<<B_, 256>>>();
  k_gramG<<<B_, 128>>>(pert);

  cudaEventRecord(ev_join, s1);
  cudaStreamWaitEvent(0, ev_join, 0);

  k_w     <<<B_, 128>>>(pert);
  k_jacobi<<<B_ / 4, 64>>>();
  k_reduce<<<1, 256>>>(out);
}

// round 15
// speedup vs baseline: 1.0232x; 1.0232x over previous
#include <cuda_runtime.h>
#include <math.h>

#define B_ 2048
#define D_ 512
#define T_ 16
#define H_ 1024
#define K_ 50
#define NSWEEP 5

// ------------------- device scratch (no allocations allowed) -------------------
__device__ float g_s[B_ * H_];        // (1 - tanh^2(z)) * W2  [B, H]
__device__ float g_grad[B_ * D_];     // grad_x                [B, D]
__device__ float g_d2[B_ * B_];       // pairwise sq distances [B, B]
__device__ float g_sq[B_];            // row squared norms
__device__ int   g_ni[B_ * K_];       // kNN indices           [B, K]
__device__ float g_G[B_ * K_ * K_];   // Gram matrices         [B, 50, 50]
__device__ float g_mean[B_ * D_];     // neighbor column means [B, 512]
__device__ float g_w[B_ * K_];        // target vector         [B, 50]
__device__ float g_res[B_];           // per-batch result

// ------------------- squared norms -------------------
__global__ __launch_bounds__(256) void k_sq(const float* __restrict__ p) {
  int w = (blockIdx.x * 256 + threadIdx.x) >> 5;
  int lane = threadIdx.x & 31;
  const float* row = p + w * D_;
  float s = 0.f;
  for (int d = lane; d < D_; d += 32) { float v = row[d]; s += v * v; }
#pragma unroll
  for (int o = 16; o > 0; o >>= 1) s += __shfl_xor_sync(0xffffffffu, s, o);
  if (lane == 0) g_sq[w] = s;
}

// ------------- GEMM 1 (128x64 tile, 8x4/thread, K-slab 16): s = (1-tanh^2)*W2 -------------
__global__ __launch_bounds__(256) void k_fwd(const float* __restrict__ xin,
                                             const float* __restrict__ tin,
                                             const float* __restrict__ W1,
                                             const float* __restrict__ b1,
                                             const float* __restrict__ W2) {
  __shared__ __align__(16) float As[16][132];   // transposed A slab: As[k][m]
  __shared__ __align__(16) float Bs[16][68];
  const int tid = threadIdx.x, tx = tid & 15, ty = tid >> 4;
  const int n0 = blockIdx.x * 64, m0 = blockIdx.y * 128;
  const int mm = tid >> 1;           // 0..127 (A-load row)
  const int kk8 = (tid & 1) * 8;     // 0 or 8 (A-load k offset)
  const int kb = tid >> 4;           // 0..15 (B-load k)
  const int nn4 = (tid & 15) * 4;    // B-load col
  float acc[8][4];
#pragma unroll
  for (int i = 0; i < 8; i++)
#pragma unroll
    for (int j = 0; j < 4; j++) acc[i][j] = 0.f;

  for (int k0 = 0; k0 < 528; k0 += 16) {
    float4 v0, v1;
    if (k0 < 512) {
      v0 = *(const float4*)&xin[(m0 + mm) * 512 + k0 + kk8];
      v1 = *(const float4*)&xin[(m0 + mm) * 512 + k0 + kk8 + 4];
    } else {
      v0 = *(const float4*)&tin[(m0 + mm) * 16 + kk8];
      v1 = *(const float4*)&tin[(m0 + mm) * 16 + kk8 + 4];
    }
    As[kk8 + 0][mm] = v0.x; As[kk8 + 1][mm] = v0.y;
    As[kk8 + 2][mm] = v0.z; As[kk8 + 3][mm] = v0.w;
    As[kk8 + 4][mm] = v1.x; As[kk8 + 5][mm] = v1.y;
    As[kk8 + 6][mm] = v1.z; As[kk8 + 7][mm] = v1.w;
    *(float4*)&Bs[kb][nn4] = *(const float4*)&W1[(k0 + kb) * 1024 + n0 + nn4];
    __syncthreads();
#pragma unroll
    for (int kk = 0; kk < 16; kk++) {
      float a[8], b[4];
      *(float4*)&a[0] = *(const float4*)&As[kk][ty * 8];
      *(float4*)&a[4] = *(const float4*)&As[kk][ty * 8 + 4];
      *(float4*)&b[0] = *(const float4*)&Bs[kk][tx * 4];
#pragma unroll
      for (int i = 0; i < 8; i++)
#pragma unroll
        for (int j = 0; j < 4; j++) acc[i][j] += a[i] * b[j];
    }
    __syncthreads();
  }
#pragma unroll
  for (int i = 0; i < 8; i++) {
    int m = m0 + ty * 8 + i;
    float o[4];
#pragma unroll
    for (int j = 0; j < 4; j++) {
      int n = n0 + tx * 4 + j;
      float z = acc[i][j] + b1[n];
      float h = tanhf(z);
      o[j] = (1.f - h * h) * W2[n];
    }
    *(float4*)&g_s[m * 1024 + n0 + tx * 4] = make_float4(o[0], o[1], o[2], o[3]);
  }
}

// ------------------- GEMM 2: grad = s @ W1[:512]^T (proven 64x64) -------------------
__global__ __launch_bounds__(256) void k_grad(const float* __restrict__ W1) {
  __shared__ __align__(16) float As[16][68];
  __shared__ __align__(16) float Bs[16][68];
  const int tid = threadIdx.x, tx = tid & 15, ty = tid >> 4;
  const int n0 = blockIdx.x * 64, m0 = blockIdx.y * 64;
  float acc[16];
#pragma unroll
  for (int i = 0; i < 16; i++) acc[i] = 0.f;
  for (int k0 = 0; k0 < 1024; k0 += 16) {
#pragma unroll
    for (int i = 0; i < 4; i++) {
      int e = tid + i * 256;
      int kk = e & 15, mm = e >> 4;
      As[kk][mm] = g_s[(m0 + mm) * 1024 + k0 + kk];
      Bs[kk][mm] = W1[(n0 + mm) * 1024 + k0 + kk];  // B[k][n] = W1[n][k]
    }
    __syncthreads();
#pragma unroll
    for (int kk = 0; kk < 16; kk++) {
      float4 a4 = *(const float4*)&As[kk][ty * 4];
      float4 b4 = *(const float4*)&Bs[kk][tx * 4];
      float av[4] = {a4.x, a4.y, a4.z, a4.w};
      float bv[4] = {b4.x, b4.y, b4.z, b4.w};
#pragma unroll
      for (int i = 0; i < 4; i++)
#pragma unroll
        for (int j = 0; j < 4; j++) acc[i * 4 + j] += av[i] * bv[j];
    }
    __syncthreads();
  }
#pragma unroll
  for (int i = 0; i < 4; i++) {
    int m = m0 + ty * 4 + i;
    *(float4*)&g_grad[m * 512 + n0 + tx * 4] =
        make_float4(acc[i * 4 + 0], acc[i * 4 + 1], acc[i * 4 + 2], acc[i * 4 + 3]);
  }
}

// ------------------- GEMM 3 (symmetric): only upper-triangle 64x64 tiles -------------------
__global__ __launch_bounds__(256) void k_d2(const float* __restrict__ p) {
  __shared__ __align__(16) float As[16][68];
  __shared__ __align__(16) float Bs[16][68];
  int bm = 0, bn;
  {
    int rem = blockIdx.x, cnt = 32;
    while (rem >= cnt) { rem -= cnt; bm++; cnt--; }
    bn = bm + rem;
  }
  const int tid = threadIdx.x, tx = tid & 15, ty = tid >> 4;
  const int m0 = bm * 64, n0 = bn * 64;
  float acc[16];
#pragma unroll
  for (int i = 0; i < 16; i++) acc[i] = 0.f;
  for (int k0 = 0; k0 < 512; k0 += 16) {
#pragma unroll
    for (int i = 0; i < 4; i++) {
      int e = tid + i * 256;
      int kk = e & 15, mm = e >> 4;
      As[kk][mm] = p[(m0 + mm) * 512 + k0 + kk];
      Bs[kk][mm] = p[(n0 + mm) * 512 + k0 + kk];
    }
    __syncthreads();
#pragma unroll
    for (int kk = 0; kk < 16; kk++) {
      float4 a4 = *(const float4*)&As[kk][ty * 4];
      float4 b4 = *(const float4*)&Bs[kk][tx * 4];
      float av[4] = {a4.x, a4.y, a4.z, a4.w};
      float bv[4] = {b4.x, b4.y, b4.z, b4.w};
#pragma unroll
      for (int i = 0; i < 4; i++)
#pragma unroll
        for (int j = 0; j < 4; j++) acc[i * 4 + j] += av[i] * bv[j];
    }
    __syncthreads();
  }
#pragma unroll
  for (int i = 0; i < 4; i++) {
    int m = m0 + ty * 4 + i;
    float sm = g_sq[m];
    float o[4];
#pragma unroll
    for (int j = 0; j < 4; j++) {
      int n = n0 + tx * 4 + j;
      o[j] = sm + g_sq[n] - 2.f * acc[i * 4 + j];
    }
    *(float4*)&g_d2[m * 2048 + n0 + tx * 4] = make_float4(o[0], o[1], o[2], o[3]);
    if (bm != bn) {
#pragma unroll
      for (int j = 0; j < 4; j++) g_d2[(n0 + tx * 4 + j) * 2048 + m] = o[j];
    }
  }
}

// ------------------- exact top-50 via 2-level radix select -------------------
__device__ __forceinline__ void find_cross(const unsigned int* hist, unsigned int target,
                                           unsigned int* warpsum,
                                           unsigned int* out_thr, unsigned int* out_base,
                                           int tid) {
  unsigned int loc[8], csum = 0;
#pragma unroll
  for (int i = 0; i < 8; i++) { loc[i] = hist[tid * 8 + i]; csum += loc[i]; }
  int lane = tid & 31, wid = tid >> 5;
  unsigned int v = csum;
#pragma unroll
  for (int o = 1; o < 32; o <<= 1) {
    unsigned int n = __shfl_up_sync(0xffffffffu, v, o);
    if (lane >= o) v += n;
  }
  if (lane == 31) warpsum[wid] = v;
  __syncthreads();
  if (tid < 8) {
    unsigned int w = warpsum[tid];
#pragma unroll
    for (int o = 1; o < 8; o <<= 1) {
      unsigned int n = __shfl_up_sync(0xffu, w, o);
      if (tid >= o) w += n;
    }
    warpsum[tid] = w;
  }
  __syncthreads();
  unsigned int excl = v - csum + (wid ? warpsum[wid - 1] : 0u);
  unsigned int run = excl;
#pragma unroll
  for (int i = 0; i < 8; i++) {
    unsigned int c2 = loc[i];
    if (run < target && run + c2 >= target) { *out_thr = tid * 8 + i; *out_base = run; }
    run += c2;
  }
  __syncthreads();
}

__global__ __launch_bounds__(256) void k_topk() {
  __shared__ unsigned int keys[2048];
  __shared__ unsigned int hist[2048];
  __shared__ unsigned int warpsum[8];
  __shared__ unsigned int s_thr1, s_base1, s_thr2, s_base2, s_cnt, s_cand;
  __shared__ unsigned int cand_key[256];
  __shared__ int cand_idx[256];

  const int row = blockIdx.x, tid = threadIdx.x;
  for (int e = tid; e < 2048; e += 256) {
    unsigned int u = __float_as_uint(g_d2[row * 2048 + e]);
    u = (u & 0x80000000u) ? ~u : (u | 0x80000000u);
    keys[e] = u;
    hist[e] = 0u;
  }
  if (tid == 0) { s_cnt = 0u; s_cand = 0u; }
  __syncthreads();
  for (int e = tid; e < 2048; e += 256) atomicAdd(&hist[keys[e] >> 21], 1u);
  __syncthreads();
  find_cross(hist, K_, warpsum, &s_thr1, &s_base1, tid);
  const unsigned int thr1 = s_thr1, base1 = s_base1;
  for (int e = tid; e < 2048; e += 256) hist[e] = 0u;
  __syncthreads();
  for (int e = tid; e < 2048; e += 256) {
    unsigned int u = keys[e];
    if ((u >> 21) == thr1) atomicAdd(&hist[(u >> 10) & 0x7FFu], 1u);
  }
  __syncthreads();
  find_cross(hist, K_ - base1, warpsum, &s_thr2, &s_base2, tid);
  const unsigned int thr10 = (thr1 << 11) | s_thr2;
  for (int e = tid; e < 2048; e += 256) {
    unsigned int u = keys[e];
    unsigned int hi = u >> 10;
    if (hi < thr10) {
      unsigned int pos = atomicAdd(&s_cnt, 1u);
      g_ni[row * K_ + pos] = e;
    } else if (hi == thr10) {
      unsigned int pos = atomicAdd(&s_cand, 1u);
      if (pos < 256u) { cand_key[pos] = u; cand_idx[pos] = e; }
    }
  }
  __syncthreads();
  const int nc = (int)min(s_cand, 256u);
  const int base = (int)s_cnt;
  const int need = K_ - base;
  if (tid < nc) {
    unsigned int ki = cand_key[tid];
    int ci = cand_idx[tid];
    int rank = 0;
    for (int j = 0; j < nc; j++) {
      unsigned int kj = cand_key[j];
      int cj = cand_idx[j];
      rank += (kj < ki) || (kj == ki && cj < ci);
    }
    if (rank < need) g_ni[row * K_ + base + rank] = ci;
  }
}

// ------------------- Gram only (needs g_ni, NOT g_grad): G + column means ----------------
__device__ __forceinline__ void accum_tile(float* acc, const float (*Cs)[132], int r0, int q0) {
#pragma unroll 4
  for (int d = 0; d < 128; d += 4) {
    float4 ar[4], br[4];
#pragma unroll
    for (int i = 0; i < 4; i++) ar[i] = *(const float4*)&Cs[r0 + i][d];
#pragma unroll
    for (int j = 0; j < 4; j++) br[j] = *(const float4*)&Cs[q0 + j][d];
#pragma unroll
    for (int i = 0; i < 4; i++)
#pragma unroll
      for (int j = 0; j < 4; j++)
        acc[i * 4 + j] += ar[i].x * br[j].x + ar[i].y * br[j].y +
                          ar[i].z * br[j].z + ar[i].w * br[j].w;
  }
}

__global__ __launch_bounds__(128) void k_gramG(const float* __restrict__ pert) {
  __shared__ __align__(16) float Cs[52][132];
  __shared__ int nidx[50];

  const int b = blockIdx.x, tid = threadIdx.x;
  if (tid < 50) nidx[tid] = g_ni[b * K_ + tid];
  for (int dd = tid; dd < 132; dd += 128) { Cs[50][dd] = 0.f; Cs[51][dd] = 0.f; }

  int tr = 0, tq = 0;
  const bool hasT = (tid < 91);
  if (hasT) {
    int rem = tid, cnt = 13;
    while (rem >= cnt) { rem -= cnt; tr++; cnt--; }
    tq = tr + rem;
  }

  float acc0[16];
#pragma unroll
  for (int i = 0; i < 16; i++) acc0[i] = 0.f;
  __syncthreads();

  for (int c = 0; c < 4; c++) {
    for (int e = tid; e < 1600; e += 128) {
      int row = e >> 5;
      int c4 = (e & 31) << 2;
      float4 v = *(const float4*)&pert[nidx[row] * 512 + c * 128 + c4];
      *(float4*)&Cs[row][c4] = v;
    }
    __syncthreads();
    {
      int d = tid;
      float sm = 0.f;
#pragma unroll 10
      for (int k = 0; k < 50; k++) sm += Cs[k][d];
      sm *= (1.0f / 50.0f);
      g_mean[b * 512 + c * 128 + d] = sm;          // export for k_w
      for (int k = 0; k < 50; k++) Cs[k][d] -= sm;
    }
    __syncthreads();
    if (hasT) accum_tile(acc0, Cs, tr * 4, tq * 4);
    __syncthreads();
  }
  float* Gout = &g_G[b * (K_ * K_)];
  if (hasT) {
    int r0 = tr * 4, q0 = tq * 4;
#pragma unroll
    for (int i = 0; i < 4; i++)
#pragma unroll
      for (int j = 0; j < 4; j++) {
        int r = r0 + i, q = q0 + j;
        if (r < 50 && q < 50) {
          float v = acc0[i * 4 + j];
          Gout[r * 50 + q] = v;
          Gout[q * 50 + r] = v;
        }
      }
  }
}

// ------------------- w = C_centered @ g  ==  dot(P_row, g) - mean.g  -------------------
__global__ __launch_bounds__(128) void k_w(const float* __restrict__ pert) {
  __shared__ __align__(16) float gsm[512];
  __shared__ int nidx[50];
  __shared__ float red[4];
  __shared__ float s_mdot;

  const int b = blockIdx.x, tid = threadIdx.x;
  const int lane = tid & 31, wq = tid >> 5;
  if (tid < 50) nidx[tid] = g_ni[b * K_ + tid];

  float part = 0.f;
  for (int d = tid; d < 512; d += 128) {
    float gv = g_grad[b * 512 + d];
    gsm[d] = gv;
    part += gv * g_mean[b * 512 + d];
  }
#pragma unroll
  for (int o = 16; o > 0; o >>= 1) part += __shfl_xor_sync(0xffffffffu, part, o);
  if (lane == 0) red[wq] = part;
  __syncthreads();
  if (tid == 0) s_mdot = (red[0] + red[1]) + (red[2] + red[3]);
  __syncthreads();
  const float mdot = s_mdot;

  for (int row = wq; row < 50; row += 4) {
    const float4* rp = (const float4*)&pert[nidx[row] * 512];
    const float4* gp = (const float4*)gsm;
    float s = 0.f;
#pragma unroll
    for (int i = lane; i < 128; i += 32) {
      float4 a = rp[i], g4 = gp[i];
      s += a.x * g4.x + a.y * g4.y + a.z * g4.z + a.w * g4.w;
    }
#pragma unroll
    for (int o = 16; o > 0; o >>= 1) s += __shfl_xor_sync(0xffffffffu, s, o);
    if (lane == 0) g_w[b * K_ + row] = s - mdot;
  }
}

// ------------------- Jacobi: FROZEN R13 version (4 problems/block, 128 threads) ----------
__global__ __launch_bounds__(128) void k_jacobi() {
  __shared__ float Gm[4][50][53];
  __shared__ float wv[4][52];
  __shared__ float2 cs[4][32];

  const int tid = threadIdx.x;
  const int W = tid >> 5;
  const int lane = tid & 31;
  const int b = blockIdx.x * 4 + W;
  float (* __restrict__ G)[53] = Gm[W];
  float* __restrict__ w = wv[W];
  float2* __restrict__ csw = cs[W];

  {
    const float* Gin = &g_G[b * (K_ * K_)];
    for (int e = lane; e < 2500; e += 32) G[e / 50][e % 50] = Gin[e];
    if (lane < 25) {
      w[lane] = g_w[b * K_ + lane];
      w[lane + 25] = g_w[b * K_ + lane + 25];
    }
  }

  int abA[10], abB[10];
#pragma unroll
  for (int it = 0; it < 10; it++) {
    int idx = lane + 32 * it;
    if (idx < 300) {
      int rem = idx, a = 0;
      while (rem >= 24 - a) { rem -= (24 - a); a++; }
      abA[it] = a;
      abB[it] = a + 1 + rem;
    } else {
      abA[it] = -1;
      abB[it] = 1;
    }
  }
  __syncwarp();

  for (int sw = 0; sw < NSWEEP; sw++) {
    for (int r = 0; r < 49; r++) {
      __syncwarp();
      float c = 1.f, s = 0.f;
      bool rot = false;
      if (lane < 25) {
        int p, q;
        if (lane == 0) { p = 49; q = r; }
        else {
          int rp_ = r + lane; p = (rp_ >= 49) ? rp_ - 49 : rp_;
          int rq_ = r - lane; q = (rq_ < 0) ? rq_ + 49 : rq_;
        }
        int mn = min(p, q), mx = max(p, q);
        float app = G[p][p], aqq = G[q][q], apq = G[mn][mx];
        rot = (apq * apq > 1e-6f * app * aqq);
        if (rot) {
          float tau = __fdividef(aqq - app, 2.0f * apq);
          float tt = __fdividef(copysignf(1.0f, tau),
                                fabsf(tau) + sqrtf(fmaf(tau, tau, 1.0f)));
          c = rsqrtf(fmaf(tt, tt, 1.0f));
          s = tt * c;
          float t00 = c * app - s * apq, t01 = c * apq - s * aqq;
          float t10 = s * app + c * apq, t11 = s * apq + c * aqq;
          G[p][p] = c * t00 - s * t01;
          G[q][q] = s * t10 + c * t11;
          G[mn][mx] = 0.0f;
          float wp = w[p], wq = w[q];
          w[p] = c * wp - s * wq;
          w[q] = s * wp + c * wq;
        }
      }
      csw[lane] = make_float2(c, s);
      unsigned int mask = __ballot_sync(0xffffffffu, rot);
      __syncwarp();
      if (mask == 0u) continue;
#pragma unroll
      for (int it = 0; it < 10; it++) {
        int a = abA[it];
        bool ok = (a >= 0);
        int aa = ok ? a : 0;
        int bb = abB[it];
        int pa, qa, pb, qb;
        if (aa == 0) { pa = 49; qa = r; }
        else {
          int v1 = r + aa; pa = (v1 >= 49) ? v1 - 49 : v1;
          int v2 = r - aa; qa = (v2 < 0) ? v2 + 49 : v2;
        }
        {
          int v1 = r + bb; pb = (v1 >= 49) ? v1 - 49 : v1;
          int v2 = r - bb; qb = (v2 < 0) ? v2 + 49 : v2;
        }
        float2 csa = csw[aa];
        float2 csb = csw[bb];
        float ca = csa.x, sa = csa.y, cb = csb.x, sb = csb.y;
        int i00 = min(pa, pb), j00 = max(pa, pb);
        int i01 = min(pa, qb), j01 = max(pa, qb);
        int i10 = min(qa, pb), j10 = max(qa, pb);
        int i11 = min(qa, qb), j11 = max(qa, qb);
        float a00 = G[i00][j00], a01 = G[i01][j01];
        float a10 = G[i10][j10], a11 = G[i11][j11];
        float t00 = ca * a00 - sa * a10, t01 = ca * a01 - sa * a11;
        float t10 = sa * a00 + ca * a10, t11 = sa * a01 + ca * a11;
        float n00 = cb * t00 - sb * t01, n01 = sb * t00 + cb * t01;
        float n10 = cb * t10 - sb * t11, n11 = sb * t10 + cb * t11;
        if (ok) {
          G[i00][j00] = n00; G[i01][j01] = n01;
          G[i10][j10] = n10; G[i11][j11] = n11;
        }
      }
    }
  }
  __syncwarp();

  float part = 0.f;
#pragma unroll
  for (int h = 0; h < 2; h++) {
    int i = lane + 32 * h;
    if (i < 50) {
      float li = G[i][i];
      int rank = 0;
#pragma unroll 10
      for (int j = 0; j < 50; j++) {
        float lj = G[j][j];
        rank += (lj > li) || (lj == li && j < i);
      }
      if (rank < 16) part += w[i] * w[i] / li;
    }
  }
#pragma unroll
  for (int o = 16; o > 0; o >>= 1) part += __shfl_xor_sync(0xffffffffu, part, o);
  if (lane == 0) g_res[b] = part;
}

// ------------------- deterministic reduce -------------------
__global__ __launch_bounds__(256) void k_reduce(float* __restrict__ out) {
  __shared__ float sm[256];
  int tid = threadIdx.x;
  float s = 0.f;
  for (int i = tid; i < B_; i += 256) s += g_res[i];
  sm[tid] = s;
  __syncthreads();
  for (int o = 128; o > 0; o >>= 1) {
    if (tid < o) sm[tid] += sm[tid + o];
    __syncthreads();
  }
  if (tid == 0) out[0] = sm[0] / (float)B_;
}

// ------------------- launch: overlap (fwd/grad || sq/d2/topk/gramG) -------------------
extern "C" void kernel_launch(void* const* d_in, const int* in_sizes, int n_in,
                              void* d_out, int out_size) {
  const float* x    = (const float*)d_in[0];
  const float* t    = (const float*)d_in[1];
  const float* pert = (const float*)d_in[2];
  const float* W1   = (const float*)d_in[3];
  const float* b1   = (const float*)d_in[4];
  const float* W2   = (const float*)d_in[5];
  float* out = (float*)d_out;

  static cudaStream_t s1 = nullptr;
  static cudaEvent_t ev_fork = nullptr, ev_join = nullptr;
  if (s1 == nullptr) {
    cudaStreamCreateWithFlags(&s1, cudaStreamNonBlocking);
    cudaEventCreateWithFlags(&ev_fork, cudaEventDisableTiming);
    cudaEventCreateWithFlags(&ev_join, cudaEventDisableTiming);
  }

  cudaEventRecord(ev_fork, 0);
  cudaStreamWaitEvent(s1, ev_fork, 0);

  // GEMM arm (s1)
  k_fwd <<<dim3(H_ / 64, B_ / 128), 256, 0, s1>>>(x, t, W1, b1, W2);
  k_grad<<<dim3(D_ / 64, B_ / 64), 256, 0, s1>>>(W1);

  // kNN arm (default)
  k_sq   <<<B_ / 8, 256>>>(pert);
  k_d2   <<<528, 256>>>(pert);
  k_topk <<<B_, 256>>>();
  k_gramG<<<B_, 128>>>(pert);

  cudaEventRecord(ev_join, s1);
  cudaStreamWaitEvent(0, ev_join, 0);

  k_w     <<<B_, 128>>>(pert);
  k_jacobi<<<B_ / 4, 128>>>();
  k_reduce<<<1, 256>>>(out);
}